// round 1
// baseline (speedup 1.0000x reference)
#include <cuda_runtime.h>

#define NND 100000
#define NE  1250000
#define HID 64

// ---------------- scratch (device globals; no allocation allowed) ----------
__device__ float g_h0[NND * HID];   // h0, later reused as h2
__device__ float g_h1[NND * HID];
__device__ float g_agg[NND * HID];
__device__ float g_inv[NND];
__device__ int   g_cnt[NND];

// ---------------- helpers ---------------------------------------------------
__global__ void zero_f4_kernel(float4* __restrict__ p, int n4) {
    int t = blockIdx.x * blockDim.x + threadIdx.x;
    if (t < n4) p[t] = make_float4(0.f, 0.f, 0.f, 0.f);
}

__global__ void zero_i_kernel(int* __restrict__ p, int n) {
    int t = blockIdx.x * blockDim.x + threadIdx.x;
    if (t < n) p[t] = 0;
}

// degree counts (same graph both layers -> compute once)
__global__ void count_kernel(const int* __restrict__ ei, int* __restrict__ cnt) {
    int e = blockIdx.x * blockDim.x + threadIdx.x;
    if (e < NE) atomicAdd(&cnt[ei[NE + e]], 1);
}

__global__ void inv_kernel(const int* __restrict__ cnt, float* __restrict__ inv) {
    int i = blockIdx.x * blockDim.x + threadIdx.x;
    if (i < NND) inv[i] = 1.0f / fmaxf((float)cnt[i], 1.0f);
}

// h0[i,:] = emb[x[i],:]   (16 threads cover one 64-float row -> coalesced f4)
__global__ void gather_kernel(const int* __restrict__ x,
                              const float* __restrict__ emb,
                              float* __restrict__ h0) {
    int t = blockIdx.x * blockDim.x + threadIdx.x;
    if (t >= NND * 16) return;
    int i = t >> 4;
    int p = (t & 15) << 2;
    int xi = __ldg(&x[i]);
    float4 v = *(const float4*)&emb[xi * HID + p];
    *(float4*)&h0[i * HID + p] = v;
}

// scatter: agg[dst,:] += h[src,:]  via red.global.add.v4.f32 (no-return atomic)
// 16 threads per edge, each thread one float4 -> 256B coalesced gather per edge
__global__ void scatter_kernel(const float* __restrict__ h,
                               const int* __restrict__ ei,
                               float* __restrict__ agg) {
    int t = blockIdx.x * blockDim.x + threadIdx.x;
    int e = t >> 4;
    if (e >= NE) return;
    int p = (t & 15) << 2;
    int src = __ldg(&ei[e]);
    int dst = __ldg(&ei[NE + e]);
    float4 v = *(const float4*)&h[src * HID + p];
    float* a = &agg[dst * HID + p];
    asm volatile("red.global.add.v4.f32 [%0], {%1, %2, %3, %4};"
                 :: "l"(a), "f"(v.x), "f"(v.y), "f"(v.z), "f"(v.w)
                 : "memory");
}

// update:
//   HAS_MEAN: out = (agg*inv) @ Wl + bl + h @ Wr, optional PReLU
//   !HAS_MEAN: out = h @ Wl + bl
// 256 threads: 16 nodes/chunk, 16 threads per node row (4 output cols each).
template<bool HAS_MEAN, bool PRELU>
__global__ void update_kernel(const float* __restrict__ h,
                              const float* __restrict__ agg,
                              const float* __restrict__ inv,
                              const float* __restrict__ Wl,
                              const float* __restrict__ bl,
                              const float* __restrict__ Wr,
                              const float* __restrict__ alpha_p,
                              float* __restrict__ out) {
    __shared__ float sWl[HID * HID];
    __shared__ float sWr[HID * HID];
    __shared__ float sb[HID];
    __shared__ float srh[16][HID];
    __shared__ float srm[16][HID];

    const int tid = threadIdx.x;   // blockDim.x == 256

    for (int i = tid; i < HID * HID; i += 256) {
        sWl[i] = Wl[i];
        if (HAS_MEAN) sWr[i] = Wr[i];
    }
    if (tid < HID) sb[tid] = bl[tid];
    float alpha = 0.f;
    if (PRELU) alpha = __ldg(alpha_p);
    __syncthreads();

    const int nchunks = NND / 16;   // 6250, exact
    for (int chunk = blockIdx.x; chunk < nchunks; chunk += gridDim.x) {
        const int base = chunk * 16;

        // stage 16 rows of h (and mean) into smem, coalesced
        for (int t = tid; t < 16 * HID; t += 256) {
            int r = t >> 6, k = t & 63;
            int node = base + r;
            srh[r][k] = h[node * HID + k];
            if (HAS_MEAN) srm[r][k] = agg[node * HID + k] * inv[node];
        }
        __syncthreads();

        const int r = tid >> 4;
        const int c = (tid & 15) << 2;
        float4 acc = *(const float4*)&sb[c];

        #pragma unroll
        for (int k = 0; k < HID; k++) {
            float hv = srh[r][k];
            float4 w = *(const float4*)&sWl[k * HID + c];
            if (HAS_MEAN) {
                float mv = srm[r][k];
                acc.x += mv * w.x; acc.y += mv * w.y;
                acc.z += mv * w.z; acc.w += mv * w.w;
                float4 w2 = *(const float4*)&sWr[k * HID + c];
                acc.x += hv * w2.x; acc.y += hv * w2.y;
                acc.z += hv * w2.z; acc.w += hv * w2.w;
            } else {
                acc.x += hv * w.x; acc.y += hv * w.y;
                acc.z += hv * w.z; acc.w += hv * w.w;
            }
        }

        if (PRELU) {
            acc.x = acc.x >= 0.f ? acc.x : alpha * acc.x;
            acc.y = acc.y >= 0.f ? acc.y : alpha * acc.y;
            acc.z = acc.z >= 0.f ? acc.z : alpha * acc.z;
            acc.w = acc.w >= 0.f ? acc.w : alpha * acc.w;
        }
        *(float4*)&out[(base + r) * HID + c] = acc;
        __syncthreads();
    }
}

// ---------------- launch -----------------------------------------------------
extern "C" void kernel_launch(void* const* d_in, const int* in_sizes, int n_in,
                              void* d_out, int out_size) {
    const int*   x    = (const int*)d_in[0];
    const int*   ei   = (const int*)d_in[1];
    // d_in[2] = edge_weight : unused by the reference
    const float* emb  = (const float*)d_in[3];
    const float* Wl1  = (const float*)d_in[4];
    const float* bl1  = (const float*)d_in[5];
    const float* Wr1  = (const float*)d_in[6];
    const float* a1   = (const float*)d_in[7];
    const float* Wl2  = (const float*)d_in[8];
    const float* bl2  = (const float*)d_in[9];
    const float* Wr2  = (const float*)d_in[10];
    const float* a2   = (const float*)d_in[11];
    const float* Wout = (const float*)d_in[12];
    const float* bout = (const float*)d_in[13];
    float* out = (float*)d_out;

    float *h0, *h1, *agg, *inv;
    int* cnt;
    cudaGetSymbolAddress((void**)&h0,  g_h0);
    cudaGetSymbolAddress((void**)&h1,  g_h1);
    cudaGetSymbolAddress((void**)&agg, g_agg);
    cudaGetSymbolAddress((void**)&inv, g_inv);
    cudaGetSymbolAddress((void**)&cnt, g_cnt);

    const int featN = NND * HID;            // 6.4M floats
    const int gz_f4 = (featN / 4 + 255) / 256;
    const int g_cnt_grid = (NND + 255) / 256;
    const int g_edge = (NE + 255) / 256;
    const int g_gather = (NND * 16 + 255) / 256;
    const int g_scatter = (NE * 16 + 255) / 256;
    const int g_update = 740;               // 5 blocks/SM * 148 SMs

    // degree counts (once)
    zero_i_kernel<<<g_cnt_grid, 256>>>(cnt, NND);
    count_kernel<<<g_edge, 256>>>(ei, cnt);
    inv_kernel<<<g_cnt_grid, 256>>>(cnt, inv);

    // h0 = emb[x]
    gather_kernel<<<g_gather, 256>>>(x, emb, h0);

    // layer 1
    zero_f4_kernel<<<gz_f4, 256>>>((float4*)agg, featN / 4);
    scatter_kernel<<<g_scatter, 256>>>(h0, ei, agg);
    update_kernel<true, true><<<g_update, 256>>>(h0, agg, inv, Wl1, bl1, Wr1, a1, h1);

    // layer 2 (h2 reuses h0 buffer)
    zero_f4_kernel<<<gz_f4, 256>>>((float4*)agg, featN / 4);
    scatter_kernel<<<g_scatter, 256>>>(h1, ei, agg);
    update_kernel<true, true><<<g_update, 256>>>(h1, agg, inv, Wl2, bl2, Wr2, a2, h0);

    // output projection
    update_kernel<false, false><<<g_update, 256>>>(h0, nullptr, nullptr, Wout, bout,
                                                   nullptr, nullptr, out);
}

// round 2
// speedup vs baseline: 1.0501x; 1.0501x over previous
#include <cuda_runtime.h>

#define NND 100000
#define NE  1250000
#define HID 64
#define NBLK_SCAN 98   // ceil(100000/1024)

// ---------------- scratch (device globals; no allocation allowed) ----------
__device__ float g_h0[NND * HID];   // h0, later reused as h2... (h2 stays fused)
__device__ float g_h1[NND * HID];
__device__ int   g_cnt[NND];
__device__ int   g_pre[NND];        // intra-block exclusive prefix
__device__ int   g_rowstart[NND];
__device__ int   g_cursor[NND];
__device__ int   g_blocksum[NBLK_SCAN];
__device__ int   g_adj[NE];

// ---------------- CSR build -------------------------------------------------
__global__ void zero_i_kernel(int* __restrict__ p, int n) {
    int t = blockIdx.x * blockDim.x + threadIdx.x;
    if (t < n) p[t] = 0;
}

__global__ void count_kernel(const int* __restrict__ ei, int* __restrict__ cnt) {
    int e = blockIdx.x * blockDim.x + threadIdx.x;
    if (e < NE) atomicAdd(&cnt[ei[NE + e]], 1);
}

// intra-block inclusive scan (Hillis-Steele, 1024 wide) -> exclusive prefix
__global__ void scan_block_kernel(const int* __restrict__ cnt,
                                  int* __restrict__ pre,
                                  int* __restrict__ blocksum) {
    __shared__ int s[1024];
    int tid = threadIdx.x;
    int gid = blockIdx.x * 1024 + tid;
    int v = (gid < NND) ? cnt[gid] : 0;
    s[tid] = v;
    __syncthreads();
    #pragma unroll
    for (int d = 1; d < 1024; d <<= 1) {
        int t = (tid >= d) ? s[tid - d] : 0;
        __syncthreads();
        s[tid] += t;
        __syncthreads();
    }
    if (gid < NND) pre[gid] = s[tid] - v;          // exclusive
    if (tid == 1023) blocksum[blockIdx.x] = s[1023];
}

__global__ void scan_tops_kernel(int* __restrict__ blocksum) {
    __shared__ int s[128];
    int tid = threadIdx.x;
    int v = (tid < NBLK_SCAN) ? blocksum[tid] : 0;
    s[tid] = v;
    __syncthreads();
    #pragma unroll
    for (int d = 1; d < 128; d <<= 1) {
        int t = (tid >= d) ? s[tid - d] : 0;
        __syncthreads();
        s[tid] += t;
        __syncthreads();
    }
    if (tid < NBLK_SCAN) blocksum[tid] = s[tid] - v;  // exclusive block offsets
}

__global__ void scan_add_kernel(const int* __restrict__ pre,
                                const int* __restrict__ blocksum,
                                int* __restrict__ rowstart,
                                int* __restrict__ cursor) {
    int i = blockIdx.x * blockDim.x + threadIdx.x;
    if (i >= NND) return;
    int st = pre[i] + blocksum[i >> 10];
    rowstart[i] = st;
    cursor[i] = st;
}

__global__ void fill_kernel(const int* __restrict__ ei,
                            int* __restrict__ cursor,
                            int* __restrict__ adj) {
    int e = blockIdx.x * blockDim.x + threadIdx.x;
    if (e >= NE) return;
    int src = ei[e];
    int dst = ei[NE + e];
    int p = atomicAdd(&cursor[dst], 1);
    adj[p] = src;
}

// ---------------- h0 = emb[x] ----------------------------------------------
__global__ void gather_kernel(const int* __restrict__ x,
                              const float* __restrict__ emb,
                              float* __restrict__ h0) {
    int t = blockIdx.x * blockDim.x + threadIdx.x;
    if (t >= NND * 16) return;
    int i = t >> 4;
    int p = (t & 15) << 2;
    int xi = __ldg(&x[i]);
    float4 v = *(const float4*)&emb[xi * HID + p];
    *(float4*)&h0[i * HID + p] = v;
}

// ---------------- fused mean-aggregate + SAGE update (+optional out proj) ---
// block = 256 threads, 16 nodes per chunk, 16 threads per node (4 cols each)
template<bool FUSE_OUT>
__global__ void sage_kernel(const float* __restrict__ h,
                            const int* __restrict__ adj,
                            const int* __restrict__ rowstart,
                            const int* __restrict__ cnt,
                            const float* __restrict__ Wl,
                            const float* __restrict__ bl,
                            const float* __restrict__ Wr,
                            const float* __restrict__ alpha_p,
                            const float* __restrict__ Wout,
                            const float* __restrict__ bout,
                            float* __restrict__ out) {
    __shared__ float sWl[HID * HID];
    __shared__ float sWr[HID * HID];
    __shared__ float sWo[FUSE_OUT ? HID * HID : 1];
    __shared__ float sb[HID];
    __shared__ float sbo[FUSE_OUT ? HID : 1];
    __shared__ float srh[16][HID];
    __shared__ float srm[16][HID];
    __shared__ float s2[FUSE_OUT ? 16 : 1][FUSE_OUT ? HID : 1];

    const int tid = threadIdx.x;

    for (int i = tid; i < HID * HID; i += 256) {
        sWl[i] = Wl[i];
        sWr[i] = Wr[i];
        if (FUSE_OUT) sWo[i] = Wout[i];
    }
    if (tid < HID) {
        sb[tid] = bl[tid];
        if (FUSE_OUT) sbo[tid] = bout[tid];
    }
    const float alpha = __ldg(alpha_p);
    __syncthreads();

    const int g = tid >> 4;            // node within chunk
    const int p = (tid & 15) << 2;     // column slice

    const int nchunks = NND / 16;      // 6250 exact
    for (int chunk = blockIdx.x; chunk < nchunks; chunk += gridDim.x) {
        const int base = chunk * 16;

        // stage self rows (coalesced)
        #pragma unroll
        for (int t = tid; t < 16 * HID; t += 256) {
            int r = t >> 6, k = t & 63;
            srh[r][k] = h[(base + r) * HID + k];
        }

        // aggregate neighbor mean directly from CSR (all loads, no atomics)
        {
            const int node = base + g;
            const int st = __ldg(&rowstart[node]);
            const int n  = __ldg(&cnt[node]);
            float4 acc = make_float4(0.f, 0.f, 0.f, 0.f);
            for (int j = 0; j < n; j++) {
                int s = __ldg(&adj[st + j]);
                float4 v = *(const float4*)&h[s * HID + p];
                acc.x += v.x; acc.y += v.y; acc.z += v.z; acc.w += v.w;
            }
            float iv = 1.0f / (float)max(n, 1);
            srm[g][p]     = acc.x * iv;
            srm[g][p + 1] = acc.y * iv;
            srm[g][p + 2] = acc.z * iv;
            srm[g][p + 3] = acc.w * iv;
        }
        __syncthreads();

        // dual GEMM: mean @ Wl + h @ Wr + bl, then PReLU
        float4 acc = *(const float4*)&sb[p];
        #pragma unroll
        for (int k = 0; k < HID; k++) {
            float mv = srm[g][k];
            float hv = srh[g][k];
            float4 w1 = *(const float4*)&sWl[k * HID + p];
            float4 w2 = *(const float4*)&sWr[k * HID + p];
            acc.x += mv * w1.x + hv * w2.x;
            acc.y += mv * w1.y + hv * w2.y;
            acc.z += mv * w1.z + hv * w2.z;
            acc.w += mv * w1.w + hv * w2.w;
        }
        acc.x = acc.x >= 0.f ? acc.x : alpha * acc.x;
        acc.y = acc.y >= 0.f ? acc.y : alpha * acc.y;
        acc.z = acc.z >= 0.f ? acc.z : alpha * acc.z;
        acc.w = acc.w >= 0.f ? acc.w : alpha * acc.w;

        if (FUSE_OUT) {
            s2[g][p] = acc.x; s2[g][p + 1] = acc.y;
            s2[g][p + 2] = acc.z; s2[g][p + 3] = acc.w;
            __syncthreads();
            float4 o = *(const float4*)&sbo[p];
            #pragma unroll
            for (int k = 0; k < HID; k++) {
                float v = s2[g][k];
                float4 w = *(const float4*)&sWo[k * HID + p];
                o.x += v * w.x; o.y += v * w.y;
                o.z += v * w.z; o.w += v * w.w;
            }
            *(float4*)&out[(base + g) * HID + p] = o;
        } else {
            *(float4*)&out[(base + g) * HID + p] = acc;
        }
        __syncthreads();
    }
}

// ---------------- launch -----------------------------------------------------
extern "C" void kernel_launch(void* const* d_in, const int* in_sizes, int n_in,
                              void* d_out, int out_size) {
    const int*   x    = (const int*)d_in[0];
    const int*   ei   = (const int*)d_in[1];
    // d_in[2] = edge_weight : unused by the reference
    const float* emb  = (const float*)d_in[3];
    const float* Wl1  = (const float*)d_in[4];
    const float* bl1  = (const float*)d_in[5];
    const float* Wr1  = (const float*)d_in[6];
    const float* a1   = (const float*)d_in[7];
    const float* Wl2  = (const float*)d_in[8];
    const float* bl2  = (const float*)d_in[9];
    const float* Wr2  = (const float*)d_in[10];
    const float* a2   = (const float*)d_in[11];
    const float* Wout = (const float*)d_in[12];
    const float* bout = (const float*)d_in[13];
    float* out = (float*)d_out;

    float *h0, *h1;
    int *cnt, *pre, *rowstart, *cursor, *blocksum, *adj;
    cudaGetSymbolAddress((void**)&h0,       g_h0);
    cudaGetSymbolAddress((void**)&h1,       g_h1);
    cudaGetSymbolAddress((void**)&cnt,      g_cnt);
    cudaGetSymbolAddress((void**)&pre,      g_pre);
    cudaGetSymbolAddress((void**)&rowstart, g_rowstart);
    cudaGetSymbolAddress((void**)&cursor,   g_cursor);
    cudaGetSymbolAddress((void**)&blocksum, g_blocksum);
    cudaGetSymbolAddress((void**)&adj,      g_adj);

    const int g_node = (NND + 255) / 256;
    const int g_edge = (NE + 255) / 256;
    const int g_gather = (NND * 16 + 255) / 256;

    // ---- CSR build (graph identical for both layers) ----
    zero_i_kernel<<<g_node, 256>>>(cnt, NND);
    count_kernel<<<g_edge, 256>>>(ei, cnt);
    scan_block_kernel<<<NBLK_SCAN, 1024>>>(cnt, pre, blocksum);
    scan_tops_kernel<<<1, 128>>>(blocksum);
    scan_add_kernel<<<g_node, 256>>>(pre, blocksum, rowstart, cursor);
    fill_kernel<<<g_edge, 256>>>(ei, cursor, adj);

    // ---- embedding gather ----
    gather_kernel<<<g_gather, 256>>>(x, emb, h0);

    // ---- layer 1 (fused aggregate + update + PReLU) ----
    sage_kernel<false><<<740, 256>>>(h0, adj, rowstart, cnt,
                                     Wl1, bl1, Wr1, a1,
                                     nullptr, nullptr, h1);

    // ---- layer 2 + output projection (h2 never hits GMEM) ----
    sage_kernel<true><<<592, 256>>>(h1, adj, rowstart, cnt,
                                    Wl2, bl2, Wr2, a2,
                                    Wout, bout, out);
}

// round 3
// speedup vs baseline: 1.6916x; 1.6109x over previous
#include <cuda_runtime.h>

#define NND 100000
#define NE  1250000
#define HID 64
#define SROW 68            // padded smem row stride (floats), 16B-aligned, bank-skewed
#define CSR_BLOCKS 98
#define CSR_THREADS 1024

// ---------------- scratch (device globals; no allocation allowed) ----------
__device__ float g_h0[NND * HID];
__device__ float g_h1[NND * HID];
__device__ int   g_cnt[NND];
__device__ int   g_rowstart[NND];
__device__ int   g_cursor[NND];
__device__ int   g_adj[NE];
__device__ int   g_blocksum[CSR_BLOCKS];
__device__ int   g_bar_count;
__device__ int   g_bar_sense;

typedef unsigned long long ull;
union F4U { float4 f; ull u[2]; };

__device__ __forceinline__ ull pack2(float v) {
    ull r; asm("mov.b64 %0, {%1, %1};" : "=l"(r) : "f"(v)); return r;
}
__device__ __forceinline__ void fma2(ull& d, ull a, ull b) {
    asm("fma.rn.f32x2 %0, %1, %2, %0;" : "+l"(d) : "l"(a), "l"(b));
}
__device__ __forceinline__ float2 unpk(ull v) {
    float2 r; asm("mov.b64 {%0, %1}, %2;" : "=f"(r.x), "=f"(r.y) : "l"(v)); return r;
}
__device__ __forceinline__ float prelu(float v, float a) { return v >= 0.f ? v : a * v; }

// ---------------- launch 1: zero cnt + reset barrier + embedding gather -----
__global__ void prep_kernel(const int* __restrict__ x,
                            const float* __restrict__ emb,
                            float* __restrict__ h0) {
    int t = blockIdx.x * blockDim.x + threadIdx.x;
    if (t < NND) g_cnt[t] = 0;
    if (t == 0) { g_bar_count = 0; g_bar_sense = 0; }
    int i = t >> 4;
    int p = (t & 15) << 2;
    int xi = __ldg(&x[i]);
    *(float4*)&h0[i * HID + p] = *(const float4*)&emb[xi * HID + p];
}

// ---------------- software grid barrier (all CSR_BLOCKS resident) -----------
__device__ __forceinline__ void grid_barrier(int phase) {
    __threadfence();
    __syncthreads();
    if (threadIdx.x == 0) {
        int v = atomicAdd(&g_bar_count, 1);
        if (v == CSR_BLOCKS - 1) {
            atomicExch(&g_bar_count, 0);
            __threadfence();
            atomicExch(&g_bar_sense, phase);
        } else {
            while (true) {
                int s;
                asm volatile("ld.global.cg.s32 %0, [%1];" : "=r"(s) : "l"(&g_bar_sense));
                if (s >= phase) break;
                __nanosleep(64);
            }
        }
    }
    __syncthreads();
}

// ---------------- launch 2: persistent CSR build (count/scan/fill) ----------
__global__ __launch_bounds__(CSR_THREADS) void csr_kernel(const int* __restrict__ ei) {
    const int tid = threadIdx.x, bid = blockIdx.x;
    const int gid = bid * CSR_THREADS + tid;
    const int gstride = CSR_BLOCKS * CSR_THREADS;

    // phase 1: degree count
    for (int e = gid; e < NE; e += gstride)
        atomicAdd(&g_cnt[__ldg(&ei[NE + e])], 1);
    grid_barrier(1);

    // phase 2: intra-block exclusive scan (shfl-based)
    __shared__ int swarp[32];
    __shared__ int soff[CSR_BLOCKS];
    int v = 0;
    if (gid < NND)
        asm volatile("ld.global.cg.s32 %0, [%1];" : "=r"(v) : "l"(&g_cnt[gid]));
    const int lane = tid & 31, wid = tid >> 5;
    int x = v;
    #pragma unroll
    for (int d = 1; d < 32; d <<= 1) { int t = __shfl_up_sync(~0u, x, d); if (lane >= d) x += t; }
    if (lane == 31) swarp[wid] = x;
    __syncthreads();
    if (wid == 0) {
        int y = swarp[lane];
        int z = y;
        #pragma unroll
        for (int d = 1; d < 32; d <<= 1) { int t = __shfl_up_sync(~0u, z, d); if (lane >= d) z += t; }
        swarp[lane] = z - y;
    }
    __syncthreads();
    const int excl = x - v + swarp[wid];
    if (tid == CSR_THREADS - 1) g_blocksum[bid] = excl + v;
    grid_barrier(2);

    // phase 3: cross-block offsets, write rowstart + cursor
    if (tid < CSR_BLOCKS) {
        int b;
        asm volatile("ld.global.cg.s32 %0, [%1];" : "=r"(b) : "l"(&g_blocksum[tid]));
        soff[tid] = b;
    }
    __syncthreads();
    if (tid == 0) {
        int run = 0;
        for (int i = 0; i < CSR_BLOCKS; i++) { int t = soff[i]; soff[i] = run; run += t; }
    }
    __syncthreads();
    if (gid < NND) {
        int st = excl + soff[bid];
        g_rowstart[gid] = st;
        g_cursor[gid] = st;
    }
    grid_barrier(3);

    // phase 4: bucket fill
    for (int e = gid; e < NE; e += gstride) {
        int src = __ldg(&ei[e]);
        int dst = __ldg(&ei[NE + e]);
        int pp = atomicAdd(&g_cursor[dst], 1);
        g_adj[pp] = src;
    }
}

// ---------------- launches 3/4: fused aggregate + dual GEMM (+out proj) -----
// 256 threads, 32 nodes/chunk. 16-lane group g owns nodes base+g, base+g+16.
// Each thread: 2 nodes x 4 cols, f32x2 packed FMA, W reused across both nodes.
template<bool FUSE_OUT>
__global__ __launch_bounds__(256, 3) void sage_kernel(
    const float* __restrict__ h,
    const float* __restrict__ Wl, const float* __restrict__ bl,
    const float* __restrict__ Wr, const float* __restrict__ alpha_p,
    const float* __restrict__ Wout, const float* __restrict__ bout,
    float* __restrict__ out)
{
    __shared__ float sWl[HID * HID];
    __shared__ float sWr[HID * HID];
    __shared__ float sWo[FUSE_OUT ? HID * HID : 1];
    __shared__ float sb[HID];
    __shared__ float sbo[FUSE_OUT ? HID : 1];
    __shared__ float srh[32 * SROW];
    __shared__ float srm[32 * SROW];
    __shared__ float sh2[FUSE_OUT ? 32 * SROW : 1];

    const int tid = threadIdx.x;
    for (int i = tid; i < HID * HID; i += 256) {
        sWl[i] = Wl[i];
        sWr[i] = Wr[i];
        if (FUSE_OUT) sWo[i] = Wout[i];
    }
    if (tid < HID) { sb[tid] = bl[tid]; if (FUSE_OUT) sbo[tid] = bout[tid]; }
    const float alpha = __ldg(alpha_p);
    __syncthreads();

    const int g = tid >> 4;
    const int lane16 = tid & 15;
    const int p4 = lane16 << 2;
    const unsigned smask = 0xFFFFu << (tid & 16);

    for (int chunk = blockIdx.x; chunk < NND / 32; chunk += gridDim.x) {
        const int base = chunk * 32;

        // stage 32 self rows (coalesced)
        #pragma unroll
        for (int t = tid; t < 32 * HID; t += 256) {
            int r = t >> 6, k = t & 63;
            srh[r * SROW + k] = h[(base + r) * HID + k];
        }

        // aggregate neighbor means: shfl-broadcast adj batches + unroll-4 row loads
        #pragma unroll
        for (int half = 0; half < 2; half++) {
            const int node = base + g + half * 16;
            const int st = __ldg(&g_rowstart[node]);
            const int n  = __ldg(&g_cnt[node]);
            float4 acc = make_float4(0.f, 0.f, 0.f, 0.f);
            for (int j = 0; j < n; j += 16) {
                const int m = min(16, n - j);
                int idx = 0;
                if (lane16 < m) idx = __ldg(&g_adj[st + j + lane16]);
                int jj = 0;
                for (; jj + 4 <= m; jj += 4) {
                    int s0 = __shfl_sync(smask, idx, jj + 0, 16);
                    int s1 = __shfl_sync(smask, idx, jj + 1, 16);
                    int s2 = __shfl_sync(smask, idx, jj + 2, 16);
                    int s3 = __shfl_sync(smask, idx, jj + 3, 16);
                    float4 v0 = *(const float4*)&h[s0 * HID + p4];
                    float4 v1 = *(const float4*)&h[s1 * HID + p4];
                    float4 v2 = *(const float4*)&h[s2 * HID + p4];
                    float4 v3 = *(const float4*)&h[s3 * HID + p4];
                    acc.x += (v0.x + v1.x) + (v2.x + v3.x);
                    acc.y += (v0.y + v1.y) + (v2.y + v3.y);
                    acc.z += (v0.z + v1.z) + (v2.z + v3.z);
                    acc.w += (v0.w + v1.w) + (v2.w + v3.w);
                }
                for (; jj < m; jj++) {
                    int s0 = __shfl_sync(smask, idx, jj, 16);
                    float4 v0 = *(const float4*)&h[s0 * HID + p4];
                    acc.x += v0.x; acc.y += v0.y; acc.z += v0.z; acc.w += v0.w;
                }
            }
            const float iv = 1.0f / (float)max(n, 1);
            *(float4*)&srm[(g + half * 16) * SROW + p4] =
                make_float4(acc.x * iv, acc.y * iv, acc.z * iv, acc.w * iv);
        }
        __syncthreads();

        // dual GEMM: (mean @ Wl + h @ Wr + bl) for 2 nodes, f32x2 packed
        const int rA = g, rB = g + 16;
        F4U bu; bu.f = *(const float4*)&sb[p4];
        ull a0 = bu.u[0], a1 = bu.u[1];
        ull b0 = bu.u[0], b1 = bu.u[1];
        #pragma unroll
        for (int k = 0; k < HID; k++) {
            F4U w1, w2;
            w1.f = *(const float4*)&sWl[k * HID + p4];
            w2.f = *(const float4*)&sWr[k * HID + p4];
            ull mA = pack2(srm[rA * SROW + k]);
            ull hA = pack2(srh[rA * SROW + k]);
            fma2(a0, mA, w1.u[0]); fma2(a1, mA, w1.u[1]);
            fma2(a0, hA, w2.u[0]); fma2(a1, hA, w2.u[1]);
            ull mB = pack2(srm[rB * SROW + k]);
            ull hB = pack2(srh[rB * SROW + k]);
            fma2(b0, mB, w1.u[0]); fma2(b1, mB, w1.u[1]);
            fma2(b0, hB, w2.u[0]); fma2(b1, hB, w2.u[1]);
        }
        float2 fa0 = unpk(a0), fa1 = unpk(a1), fb0 = unpk(b0), fb1 = unpk(b1);
        fa0.x = prelu(fa0.x, alpha); fa0.y = prelu(fa0.y, alpha);
        fa1.x = prelu(fa1.x, alpha); fa1.y = prelu(fa1.y, alpha);
        fb0.x = prelu(fb0.x, alpha); fb0.y = prelu(fb0.y, alpha);
        fb1.x = prelu(fb1.x, alpha); fb1.y = prelu(fb1.y, alpha);

        if (FUSE_OUT) {
            *(float4*)&sh2[rA * SROW + p4] = make_float4(fa0.x, fa0.y, fa1.x, fa1.y);
            *(float4*)&sh2[rB * SROW + p4] = make_float4(fb0.x, fb0.y, fb1.x, fb1.y);
            __syncthreads();
            F4U ou; ou.f = *(const float4*)&sbo[p4];
            ull oa0 = ou.u[0], oa1 = ou.u[1];
            ull ob0 = ou.u[0], ob1 = ou.u[1];
            #pragma unroll
            for (int k = 0; k < HID; k++) {
                F4U wo;
                wo.f = *(const float4*)&sWo[k * HID + p4];
                ull vA = pack2(sh2[rA * SROW + k]);
                ull vB = pack2(sh2[rB * SROW + k]);
                fma2(oa0, vA, wo.u[0]); fma2(oa1, vA, wo.u[1]);
                fma2(ob0, vB, wo.u[0]); fma2(ob1, vB, wo.u[1]);
            }
            float2 g0 = unpk(oa0), g1 = unpk(oa1), g2 = unpk(ob0), g3 = unpk(ob1);
            *(float4*)&out[(base + rA) * HID + p4] = make_float4(g0.x, g0.y, g1.x, g1.y);
            *(float4*)&out[(base + rB) * HID + p4] = make_float4(g2.x, g2.y, g3.x, g3.y);
        } else {
            *(float4*)&out[(base + rA) * HID + p4] = make_float4(fa0.x, fa0.y, fa1.x, fa1.y);
            *(float4*)&out[(base + rB) * HID + p4] = make_float4(fb0.x, fb0.y, fb1.x, fb1.y);
        }
        __syncthreads();
    }
}

// ---------------- launch -----------------------------------------------------
extern "C" void kernel_launch(void* const* d_in, const int* in_sizes, int n_in,
                              void* d_out, int out_size) {
    const int*   x    = (const int*)d_in[0];
    const int*   ei   = (const int*)d_in[1];
    // d_in[2] = edge_weight : unused by the reference
    const float* emb  = (const float*)d_in[3];
    const float* Wl1  = (const float*)d_in[4];
    const float* bl1  = (const float*)d_in[5];
    const float* Wr1  = (const float*)d_in[6];
    const float* a1   = (const float*)d_in[7];
    const float* Wl2  = (const float*)d_in[8];
    const float* bl2  = (const float*)d_in[9];
    const float* Wr2  = (const float*)d_in[10];
    const float* a2   = (const float*)d_in[11];
    const float* Wout = (const float*)d_in[12];
    const float* bout = (const float*)d_in[13];
    float* out = (float*)d_out;

    float *h0, *h1;
    cudaGetSymbolAddress((void**)&h0, g_h0);
    cudaGetSymbolAddress((void**)&h1, g_h1);

    // 4 launches total -> ncu (4th-launch capture) profiles sage_kernel<true>
    prep_kernel<<<(NND * 16) / 256, 256>>>(x, emb, h0);
    csr_kernel<<<CSR_BLOCKS, CSR_THREADS>>>(ei);
    sage_kernel<false><<<444, 256>>>(h0, Wl1, bl1, Wr1, a1, nullptr, nullptr, h1);
    sage_kernel<true><<<444, 256>>>(h1, Wl2, bl2, Wr2, a2, Wout, bout, out);
}